// round 11
// baseline (speedup 1.0000x reference)
#include <cuda_runtime.h>

// Fixed problem shape: B=512, Np=128, Ng=128, TIME=5
#define BATCH 512
#define NP 128
#define NG 128
#define TSTEPS 5
#define NSEG 128                  // segments (one per gt vertex)
#define NSLICE 4                  // segment slices per pred
#define SEGS_PER_SLICE (NSEG / NSLICE)       // 32
#define PAIRS_PER_SLICE (SEGS_PER_SLICE / 2) // 16
#define PREDS_PER_CTA 64
#define CTA_THREADS 256           // 64 preds x 4 slices
#define NCTA (BATCH * (NP / PREDS_PER_CTA))  // 1024

__device__ float        g_partial[NCTA];
__device__ unsigned int g_count = 0;

// ---------- packed f32x2 helpers (sm_103a: add/mul/fma only!) ----------
__device__ __forceinline__ unsigned long long pk2(float lo, float hi) {
    unsigned long long r;
    asm("mov.b64 %0, {%1, %2};" : "=l"(r) : "f"(lo), "f"(hi));
    return r;
}
__device__ __forceinline__ unsigned long long add2(unsigned long long a, unsigned long long b) {
    unsigned long long r;
    asm("add.rn.f32x2 %0, %1, %2;" : "=l"(r) : "l"(a), "l"(b));
    return r;
}
__device__ __forceinline__ unsigned long long mul2(unsigned long long a, unsigned long long b) {
    unsigned long long r;
    asm("mul.rn.f32x2 %0, %1, %2;" : "=l"(r) : "l"(a), "l"(b));
    return r;
}
__device__ __forceinline__ unsigned long long fma2(unsigned long long a, unsigned long long b,
                                                   unsigned long long c) {
    unsigned long long r;
    asm("fma.rn.f32x2 %0, %1, %2, %3;" : "=l"(r) : "l"(a), "l"(b), "l"(c));
    return r;
}
__device__ __forceinline__ float lo2(unsigned long long v) {
    return __uint_as_float((unsigned int)v);
}
__device__ __forceinline__ float hi2(unsigned long long v) {
    return __uint_as_float((unsigned int)(v >> 32));
}

__device__ __forceinline__ float smooth_l1_elem(float d) {
    d = fabsf(d);
    return (d < 1.0f) ? (0.5f * d * d) : (d - 0.5f);
}

#define RMAGIC 12582912.0f   // 1.5 * 2^23: (u+RMAGIC)-RMAGIC = round-to-nearest int

// Two CTAs per batch (64 preds each). Thread (sl = tid>>6, q = tid&63) scans
// segment slice [32*sl, 32*sl+32) analytically: D(k) = |e|^2 + k*dm' + k^2*d2s
// with k = clamp(round(u), 0, 4); math packed f32x2 (two segments per lane),
// clamp scalar (FMNMX — no packed min/max exists in PTX).
__global__ void __launch_bounds__(CTA_THREADS, 7)
dm_fused(const float2* __restrict__ pred,
         const float2* __restrict__ gt,
         float* __restrict__ out) {
    // Raw gt vertices (for exact matched-point reconstruction at the end).
    __shared__ __align__(16) float2 gtv[NG];                 // 1 KB
    // Per-segment analytic data, packed for f32x2 pair processing:
    // A4[p] = {-ax[2p], -ax[2p+1], -ay[2p], -ay[2p+1]}
    // D4[p] = {dpx[2p], dpx[2p+1], dpy[2p], dpy[2p+1]}   dp  = -0.4*d (= -2d/5)
    // Q4[p] = {qq[2p],  qq[2p+1],  d2s[2p], d2s[2p+1]}   qq = -12.5/d2, d2s = d2/25
    __shared__ __align__(16) float A4[NSEG / 2 * 4];
    __shared__ __align__(16) float D4[NSEG / 2 * 4];
    __shared__ __align__(16) float Q4[NSEG / 2 * 4];
    __shared__ unsigned int s_amin[NSLICE][PREDS_PER_CTA];
    __shared__ float s_warp[2];
    __shared__ int   s_is_last;

    const int cta  = blockIdx.x;
    const int b    = cta >> 1;
    const int half = cta & 1;
    const int tid  = threadIdx.x;
    const int q    = tid & 63;      // pred id within CTA
    const int sl   = tid >> 6;      // slice id 0..3
    const float2* gtb = gt + b * NG;

    // Build per-segment analytic data (one thread per segment).
    if (tid < NSEG) {
        int n = tid;
        float2 c = __ldg(&gtb[n]);
        float2 a = __ldg(&gtb[(n + NG - 1) & (NG - 1)]);
        gtv[n] = c;
        float dx = c.x - a.x, dy = c.y - a.y;
        float d2 = dx * dx + dy * dy;
        int pr = n >> 1, pa = n & 1;
        A4[4 * pr + pa]     = -a.x;
        A4[4 * pr + 2 + pa] = -a.y;
        D4[4 * pr + pa]     = -0.4f * dx;
        D4[4 * pr + 2 + pa] = -0.4f * dy;
        Q4[4 * pr + pa]     = -12.5f / d2;
        Q4[4 * pr + 2 + pa] = d2 * 0.04f;
    }
    __syncthreads();

    const float2 pp = pred[b * NP + half * PREDS_PER_CTA + q];
    const unsigned long long px2   = pk2(pp.x, pp.x);
    const unsigned long long py2   = pk2(pp.y, pp.y);
    const unsigned long long MAG2  = pk2(RMAGIC, RMAGIC);
    const unsigned long long NMAG2 = pk2(-RMAGIC, -RMAGIC);

    // Key: (analytic_min_dist_bits & 0xFFFFFF80) | j  (j = pair index, 0..15).
    unsigned int accE = 0xFFFFFFFFu, accO = 0xFFFFFFFFu;

    const int pair0 = sl * PAIRS_PER_SLICE;
    const ulonglong2* A2v = reinterpret_cast<const ulonglong2*>(A4) + pair0;
    const ulonglong2* D2v = reinterpret_cast<const ulonglong2*>(D4) + pair0;
    const ulonglong2* Q2v = reinterpret_cast<const ulonglong2*>(Q4) + pair0;

    #pragma unroll 8
    for (unsigned int j = 0; j < PAIRS_PER_SLICE; ++j) {
        ulonglong2 av = A2v[j];  // (-ax pair, -ay pair)
        ulonglong2 dv = D2v[j];  // (dp.x pair, dp.y pair)
        ulonglong2 qv = Q2v[j];  // (qq pair, d2/25 pair)
        unsigned long long ex2 = add2(px2, av.x);                  // e = p - a
        unsigned long long ey2 = add2(py2, av.y);
        unsigned long long dm2 = fma2(ey2, dv.y, mul2(ex2, dv.x)); // dm' = -2 e.d/5
        unsigned long long e22 = fma2(ey2, ey2, mul2(ex2, ex2));   // |e|^2
        unsigned long long u2  = mul2(dm2, qv.x);                  // 5 e.d / d2
        unsigned long long r2  = add2(add2(u2, MAG2), NMAG2);      // round(u)
        // scalar clamp (NaN from degenerate d2=0 clamps to 0 via fmaxf)
        float k0 = fminf(fmaxf(lo2(r2), 0.0f), 4.0f);
        float k1 = fminf(fmaxf(hi2(r2), 0.0f), 4.0f);
        unsigned long long kf2 = pk2(k0, k1);
        unsigned long long Dd2 = fma2(kf2, fma2(kf2, qv.y, dm2), e22);
        accE = min(accE, (((unsigned int)Dd2)         & 0xFFFFFF80u) | j);
        accO = min(accO, (((unsigned int)(Dd2 >> 32)) & 0xFFFFFF80u) | j);
    }
    // Rebuild keys with global segment index n (7 bits) in the low field.
    const unsigned int base0 = (unsigned int)(sl * SEGS_PER_SLICE);
    unsigned int keyE = (accE & 0xFFFFFF80u) | (base0 + ((accE & 0x7Fu) << 1));
    unsigned int keyO = (accO & 0xFFFFFF80u) | (base0 + ((accO & 0x7Fu) << 1) + 1u);
    s_amin[sl][q] = min(keyE, keyO);
    __syncthreads();

    if (tid < PREDS_PER_CTA) {   // q == tid, pp is this pred point
        unsigned int best = min(min(s_amin[0][tid], s_amin[1][tid]),
                                min(s_amin[2][tid], s_amin[3][tid]));
        int n  = (int)(best & 0x7Fu);
        int pr = n >> 1, pa = n & 1;
        // recompute kf for the winning segment
        float ex = pp.x + A4[4 * pr + pa];
        float ey = pp.y + A4[4 * pr + 2 + pa];
        float dm = fmaf(ey, D4[4 * pr + 2 + pa], ex * D4[4 * pr + pa]);
        float u  = dm * Q4[4 * pr + pa];
        float kf = fminf(fmaxf((u + RMAGIC) - RMAGIC, 0.0f), 4.0f);
        float s  = kf * 0.2f;                 // == t/5 in fp32 for k = 0..4
        float2 c = gtv[n];
        float2 a = gtv[(n + NG - 1) & (NG - 1)];
        float mx = c.x * s + a.x * (1.0f - s);   // exact reference formula
        float my = c.y * s + a.y * (1.0f - s);
        float l = smooth_l1_elem(pp.x - mx) + smooth_l1_elem(pp.y - my);
        #pragma unroll
        for (int o = 16; o > 0; o >>= 1)
            l += __shfl_xor_sync(0xFFFFFFFFu, l, o);
        if ((tid & 31) == 0) s_warp[tid >> 5] = l;
    }
    __syncthreads();

    if (tid == 0) {
        g_partial[cta] = s_warp[0] + s_warp[1];
        __threadfence();
        unsigned int old = atomicAdd(&g_count, 1u);
        s_is_last = (old == (unsigned int)(gridDim.x - 1));
    }
    __syncthreads();

    if (s_is_last && tid < 32) {
        __threadfence();
        // Single-warp deterministic final reduction: fixed per-lane order,
        // fixed butterfly. 32 L2 loads per lane issued back-to-back (MLP).
        float s = 0.0f;
        #pragma unroll
        for (int i = 0; i < 32; ++i)
            s += __ldcg(&g_partial[tid + 32 * i]);
        #pragma unroll
        for (int o = 16; o > 0; o >>= 1)
            s += __shfl_xor_sync(0xFFFFFFFFu, s, o);
        if (tid == 0) {
            out[0] = s * (1.0f / (float)(BATCH * NP * 2));
            g_count = 0;   // reset for next graph replay
        }
    }
}

extern "C" void kernel_launch(void* const* d_in, const int* in_sizes, int n_in,
                              void* d_out, int out_size) {
    const float2* pred = (const float2*)d_in[1];
    const float2* gt   = (const float2*)d_in[2];
    dm_fused<<<NCTA, CTA_THREADS>>>(pred, gt, (float*)d_out);
}

// round 12
// speedup vs baseline: 1.0205x; 1.0205x over previous
#include <cuda_runtime.h>

// Fixed problem shape: B=512, Np=128, Ng=128, TIME=5
#define BATCH 512
#define NP 128
#define NG 128
#define TSTEPS 5
#define NSEG 128                  // segments (one per gt vertex)
#define NSLICE 4                  // segment slices per pred
#define SEGS_PER_SLICE (NSEG / NSLICE)       // 32
#define PAIRS_PER_SLICE (SEGS_PER_SLICE / 2) // 16
#define CTA_THREADS 256           // 64 pred-pairs x 4 slices

__device__ float        g_partial[BATCH];
__device__ unsigned int g_count = 0;

// ---------- packed f32x2 helpers (sm_103a: add/mul/fma only) ----------
__device__ __forceinline__ unsigned long long pk2(float lo, float hi) {
    unsigned long long r;
    asm("mov.b64 %0, {%1, %2};" : "=l"(r) : "f"(lo), "f"(hi));
    return r;
}
__device__ __forceinline__ unsigned long long add2(unsigned long long a, unsigned long long b) {
    unsigned long long r;
    asm("add.rn.f32x2 %0, %1, %2;" : "=l"(r) : "l"(a), "l"(b));
    return r;
}
__device__ __forceinline__ unsigned long long mul2(unsigned long long a, unsigned long long b) {
    unsigned long long r;
    asm("mul.rn.f32x2 %0, %1, %2;" : "=l"(r) : "l"(a), "l"(b));
    return r;
}
__device__ __forceinline__ unsigned long long fma2(unsigned long long a, unsigned long long b,
                                                   unsigned long long c) {
    unsigned long long r;
    asm("fma.rn.f32x2 %0, %1, %2, %3;" : "=l"(r) : "l"(a), "l"(b), "l"(c));
    return r;
}
__device__ __forceinline__ float lo2(unsigned long long v) {
    return __uint_as_float((unsigned int)v);
}
__device__ __forceinline__ float hi2(unsigned long long v) {
    return __uint_as_float((unsigned int)(v >> 32));
}

__device__ __forceinline__ float smooth_l1_elem(float d) {
    d = fabsf(d);
    return (d < 1.0f) ? (0.5f * d * d) : (d - 0.5f);
}

#define RMAGIC 12582912.0f   // 1.5 * 2^23: (u+RMAGIC)-RMAGIC = round-to-nearest int

// One CTA per batch. Thread (sl = tid>>6, q = tid&63) scans segment slice
// [32*sl, 32*sl+32) analytically for pred points 2q and 2q+1. Each table
// LDS.128 trio serves TWO preds (the smem crossbar is the measured floor).
__global__ void __launch_bounds__(CTA_THREADS, 4)
dm_fused(const float2* __restrict__ pred,
         const float2* __restrict__ gt,
         float* __restrict__ out) {
    __shared__ __align__(16) float2 gtv[NG];   // raw gt vertices (1 KB)
    // Per-segment analytic data, packed for f32x2 pair processing:
    // A4[p] = {-ax[2p], -ax[2p+1], -ay[2p], -ay[2p+1]}
    // D4[p] = {dpx[2p], dpx[2p+1], dpy[2p], dpy[2p+1]}   dp  = -0.4*d (= -2d/5)
    // Q4[p] = {qq[2p],  qq[2p+1],  d2s[2p], d2s[2p+1]}   qq = -12.5/d2, d2s = d2/25
    __shared__ __align__(16) float A4[NSEG / 2 * 4];
    __shared__ __align__(16) float D4[NSEG / 2 * 4];
    __shared__ __align__(16) float Q4[NSEG / 2 * 4];
    __shared__ unsigned int s_amin[NSLICE][NP];
    __shared__ float s_warp[4];
    __shared__ int   s_is_last;

    const int b   = blockIdx.x;
    const int tid = threadIdx.x;
    const int q   = tid & 63;      // pred-pair id (preds 2q, 2q+1)
    const int sl  = tid >> 6;      // slice id 0..3
    const float2* gtb = gt + b * NG;

    // Build per-segment analytic data (one thread per segment).
    if (tid < NSEG) {
        int n = tid;
        float2 c = __ldg(&gtb[n]);
        float2 a = __ldg(&gtb[(n + NG - 1) & (NG - 1)]);
        gtv[n] = c;
        float dx = c.x - a.x, dy = c.y - a.y;
        float d2 = dx * dx + dy * dy;
        int pr = n >> 1, pa = n & 1;
        A4[4 * pr + pa]     = -a.x;
        A4[4 * pr + 2 + pa] = -a.y;
        D4[4 * pr + pa]     = -0.4f * dx;
        D4[4 * pr + 2 + pa] = -0.4f * dy;
        Q4[4 * pr + pa]     = -12.5f / d2;
        Q4[4 * pr + 2 + pa] = d2 * 0.04f;
    }
    __syncthreads();

    const float2 pA = pred[b * NP + 2 * q + 0];
    const float2 pB = pred[b * NP + 2 * q + 1];
    const unsigned long long pxA = pk2(pA.x, pA.x), pyA = pk2(pA.y, pA.y);
    const unsigned long long pxB = pk2(pB.x, pB.x), pyB = pk2(pB.y, pB.y);
    const unsigned long long MAG2  = pk2(RMAGIC, RMAGIC);
    const unsigned long long NMAG2 = pk2(-RMAGIC, -RMAGIC);

    // Key: (analytic_min_dist_bits & 0xFFFFFF80) | j  (j = pair index, 0..15).
    unsigned int aEA = 0xFFFFFFFFu, aOA = 0xFFFFFFFFu;
    unsigned int aEB = 0xFFFFFFFFu, aOB = 0xFFFFFFFFu;

    const int pair0 = sl * PAIRS_PER_SLICE;
    const ulonglong2* A2v = reinterpret_cast<const ulonglong2*>(A4) + pair0;
    const ulonglong2* D2v = reinterpret_cast<const ulonglong2*>(D4) + pair0;
    const ulonglong2* Q2v = reinterpret_cast<const ulonglong2*>(Q4) + pair0;

    #pragma unroll 8
    for (unsigned int j = 0; j < PAIRS_PER_SLICE; ++j) {
        ulonglong2 av = A2v[j];  // (-ax pair, -ay pair)        — shared by A & B
        ulonglong2 dv = D2v[j];  // (dp.x pair, dp.y pair)
        ulonglong2 qv = Q2v[j];  // (qq pair, d2/25 pair)
        // pred A
        {
            unsigned long long ex2 = add2(pxA, av.x);
            unsigned long long ey2 = add2(pyA, av.y);
            unsigned long long dm2 = fma2(ey2, dv.y, mul2(ex2, dv.x));
            unsigned long long e22 = fma2(ey2, ey2, mul2(ex2, ex2));
            unsigned long long u2  = mul2(dm2, qv.x);
            unsigned long long r2  = add2(add2(u2, MAG2), NMAG2);
            float k0 = fminf(fmaxf(lo2(r2), 0.0f), 4.0f);
            float k1 = fminf(fmaxf(hi2(r2), 0.0f), 4.0f);
            unsigned long long kf2 = pk2(k0, k1);
            unsigned long long Dd2 = fma2(kf2, fma2(kf2, qv.y, dm2), e22);
            aEA = min(aEA, (((unsigned int)Dd2)         & 0xFFFFFF80u) | j);
            aOA = min(aOA, (((unsigned int)(Dd2 >> 32)) & 0xFFFFFF80u) | j);
        }
        // pred B
        {
            unsigned long long ex2 = add2(pxB, av.x);
            unsigned long long ey2 = add2(pyB, av.y);
            unsigned long long dm2 = fma2(ey2, dv.y, mul2(ex2, dv.x));
            unsigned long long e22 = fma2(ey2, ey2, mul2(ex2, ex2));
            unsigned long long u2  = mul2(dm2, qv.x);
            unsigned long long r2  = add2(add2(u2, MAG2), NMAG2);
            float k0 = fminf(fmaxf(lo2(r2), 0.0f), 4.0f);
            float k1 = fminf(fmaxf(hi2(r2), 0.0f), 4.0f);
            unsigned long long kf2 = pk2(k0, k1);
            unsigned long long Dd2 = fma2(kf2, fma2(kf2, qv.y, dm2), e22);
            aEB = min(aEB, (((unsigned int)Dd2)         & 0xFFFFFF80u) | j);
            aOB = min(aOB, (((unsigned int)(Dd2 >> 32)) & 0xFFFFFF80u) | j);
        }
    }
    // Rebuild keys with global segment index n (7 bits) in the low field.
    const unsigned int base0 = (unsigned int)(sl * SEGS_PER_SLICE);
    {
        unsigned int kE = (aEA & 0xFFFFFF80u) | (base0 + ((aEA & 0x7Fu) << 1));
        unsigned int kO = (aOA & 0xFFFFFF80u) | (base0 + ((aOA & 0x7Fu) << 1) + 1u);
        s_amin[sl][2 * q + 0] = min(kE, kO);
    }
    {
        unsigned int kE = (aEB & 0xFFFFFF80u) | (base0 + ((aEB & 0x7Fu) << 1));
        unsigned int kO = (aOB & 0xFFFFFF80u) | (base0 + ((aOB & 0x7Fu) << 1) + 1u);
        s_amin[sl][2 * q + 1] = min(kE, kO);
    }
    __syncthreads();

    if (tid < NP) {   // one thread per pred point
        unsigned int best = min(min(s_amin[0][tid], s_amin[1][tid]),
                                min(s_amin[2][tid], s_amin[3][tid]));
        int n  = (int)(best & 0x7Fu);
        int pr = n >> 1, pa = n & 1;
        float2 pp = __ldg(&pred[b * NP + tid]);
        // recompute kf for the winning segment
        float ex = pp.x + A4[4 * pr + pa];
        float ey = pp.y + A4[4 * pr + 2 + pa];
        float dm = fmaf(ey, D4[4 * pr + 2 + pa], ex * D4[4 * pr + pa]);
        float u  = dm * Q4[4 * pr + pa];
        float kf = fminf(fmaxf((u + RMAGIC) - RMAGIC, 0.0f), 4.0f);
        float s  = kf * 0.2f;                 // == t/5 in fp32 for k = 0..4
        float2 c = gtv[n];
        float2 a = gtv[(n + NG - 1) & (NG - 1)];
        float mx = c.x * s + a.x * (1.0f - s);   // exact reference formula
        float my = c.y * s + a.y * (1.0f - s);
        float l = smooth_l1_elem(pp.x - mx) + smooth_l1_elem(pp.y - my);
        #pragma unroll
        for (int o = 16; o > 0; o >>= 1)
            l += __shfl_xor_sync(0xFFFFFFFFu, l, o);
        if ((tid & 31) == 0) s_warp[tid >> 5] = l;
    }
    __syncthreads();

    if (tid == 0) {
        g_partial[b] = (s_warp[0] + s_warp[1]) + (s_warp[2] + s_warp[3]);
        __threadfence();
        unsigned int old = atomicAdd(&g_count, 1u);
        s_is_last = (old == (unsigned int)(gridDim.x - 1));
    }
    __syncthreads();

    if (s_is_last && tid < 32) {
        __threadfence();
        // Single-warp deterministic final reduction: fixed per-lane order,
        // fixed butterfly. 16 back-to-back L2 loads per lane (MLP-covered).
        float s = 0.0f;
        #pragma unroll
        for (int i = 0; i < 16; ++i)
            s += __ldcg(&g_partial[tid + 32 * i]);
        #pragma unroll
        for (int o = 16; o > 0; o >>= 1)
            s += __shfl_xor_sync(0xFFFFFFFFu, s, o);
        if (tid == 0) {
            out[0] = s * (1.0f / (float)(BATCH * NP * 2));
            g_count = 0;   // reset for next graph replay
        }
    }
}

extern "C" void kernel_launch(void* const* d_in, const int* in_sizes, int n_in,
                              void* d_out, int out_size) {
    const float2* pred = (const float2*)d_in[1];
    const float2* gt   = (const float2*)d_in[2];
    dm_fused<<<BATCH, CTA_THREADS>>>(pred, gt, (float*)d_out);
}